// round 15
// baseline (speedup 1.0000x reference)
#include <cuda_runtime.h>
#include <math.h>
#include <stdint.h>

#define BN   65536
#define NPB  16384
#define NE   262144
#define EPB  128

// g_Bp: 14 K32-chunks x 128 n x 24 words (bf16x2 pairs, pair-slot interleaved)
__device__ __align__(16) float g_P [(size_t)BN * 128];
__device__ __align__(16) float g_dh[(size_t)BN * 64];
__device__ __align__(16) float g_dx[(size_t)BN * 3];
__device__ __align__(16) float g_Bp[14 * 128 * 24];
__device__ __align__(16) float g_W2p[64 * 40];
// h image: [4 chunks][BN nodes][16 words] bf16x2 pair-interleaved (16 MB)
__device__ __align__(16) float g_Ah[(size_t)4 * BN * 16];

__device__ __forceinline__ float silu_f(float v) {
    return v * (1.0f / (1.0f + __expf(-v)));
}
__device__ __forceinline__ uint32_t pack_bf16(float lo, float hi) {
    uint32_t r;
    asm("cvt.rn.bf16x2.f32 %0, %1, %2;" : "=r"(r) : "f"(hi), "f"(lo));
    return r;
}
__device__ __forceinline__ void mma_bf16(float* c, const uint32_t* a, const uint32_t* b) {
    asm volatile("mma.sync.aligned.m16n8k16.row.col.f32.bf16.bf16.f32 "
        "{%0,%1,%2,%3}, {%4,%5,%6,%7}, {%8,%9}, {%0,%1,%2,%3};"
        : "+f"(c[0]), "+f"(c[1]), "+f"(c[2]), "+f"(c[3])
        : "r"(a[0]), "r"(a[1]), "r"(a[2]), "r"(a[3]), "r"(b[0]), "r"(b[1]));
}
__device__ __forceinline__ void red_add_v2(float* p, float a, float b) {
    asm volatile("red.global.add.v2.f32 [%0], {%1,%2};"
                 :: "l"(p), "f"(a), "f"(b) : "memory");
}
__device__ __forceinline__ void cp_async16(uint32_t dst, const void* src) {
    asm volatile("cp.async.cg.shared.global [%0], [%1], 16;" :: "r"(dst), "l"(src));
}

// ---------------- prep: weights + h image -----------------------------------
__global__ void prep_kernel(const float* __restrict__ pw1,
                            const float* __restrict__ hw1,
                            const float* __restrict__ hw2,
                            const float* __restrict__ pw2,
                            const float* __restrict__ h)
{
    const int stride = gridDim.x * blockDim.x;
    const int idx0 = blockIdx.x * blockDim.x + threadIdx.x;
    for (int i = idx0; i < 14 * 128 * 24; i += stride) {
        const int w = i % 24, n = (i / 24) & 127, c = i / (24 * 128);
        float v = 0.f;
        if (w < 16) {
            const int g = w >> 3, s = w & 7;
            const int p = (s >> 1) + ((s & 1) << 2);
            const int kl = 16 * g + 2 * p;
            float lo, hi;
            if (c < 4) {
                const int k = c * 32 + kl;
                if (n < 64) { lo = pw1[k * 64 + n];         hi = pw1[(k + 1) * 64 + n]; }
                else        { lo = pw1[(128 + k) * 64 + (n - 64)];
                              hi = pw1[(129 + k) * 64 + (n - 64)]; }
            } else if (c < 10) {
                const int k = (c - 4) * 32 + kl;
                lo = hw1[k * 128 + n]; hi = hw1[(k + 1) * 128 + n];
            } else {
                const int k = (c - 10) * 32 + kl;
                lo = hw2[k * 128 + n]; hi = hw2[(k + 1) * 128 + n];
            }
            v = __uint_as_float(pack_bf16(lo, hi));
        }
        g_Bp[i] = v;
    }
    for (int i = idx0; i < 64 * 40; i += stride) {
        const int w = i % 40, n = i / 40;
        float v = 0.f;
        if (w < 32) {
            const int g = w >> 3, s = w & 7;
            const int p = (s >> 1) + ((s & 1) << 2);
            const int k = 16 * g + 2 * p;
            v = __uint_as_float(pack_bf16(pw2[k * 64 + n], pw2[(k + 1) * 64 + n]));
        }
        g_W2p[i] = v;
    }
    // h image: item = (chunk c, node nd, seg s of 4 words)
    // words s*4+j: k pairs  base+{0,8,2,10}+... per interleave map
    for (int i = idx0; i < 4 * BN * 4; i += stride) {
        const int s  = i & 3;
        const int nd = (i >> 2) & (BN - 1);
        const int c  = i >> 20;                 // 4*BN/4 ... BN*4 = 1<<18; i>>18&3? careful
        // NOTE: i = ((c*BN + nd) << 2) | s  -> c = i >> 20 only if BN = 1<<18/4.
        // Use explicit decode instead:
        const int cn = i >> 2;                  // c*BN + nd
        const int cc = cn >> 16;                // BN = 65536
        const int node = cn & (BN - 1);
        const int ag = s >> 1, half = s & 1;
        const float* src = h + (size_t)node * 128 + cc * 32 + ag * 16;
        const float4 lo4 = *(const float4*)(src + half * 4);
        const float4 hi4 = *(const float4*)(src + 8 + half * 4);
        uint4 w;
        w.x = pack_bf16(lo4.x, lo4.y);
        w.y = pack_bf16(hi4.x, hi4.y);
        w.z = pack_bf16(lo4.z, lo4.w);
        w.w = pack_bf16(hi4.z, hi4.w);
        *(uint4*)(g_Ah + ((size_t)cn * 16) + s * 4) = w;
        (void)nd; (void)c;
    }
}

// ============ gemm_p: bf16 CTA 128x128, all-cp.async + zero tail ============
__global__ __launch_bounds__(256, 2) void gemm_p()
{
    extern __shared__ float sm[];
    const int BUFW = 6144;                       // A @0 (3072w), B @3072 (3072w)

    if (blockIdx.x >= 512) {          // zero g_dh / g_dx (overlaps P compute)
        const int t0 = (blockIdx.x - 512) * 256 + threadIdx.x;
        float4 z = make_float4(0.f, 0.f, 0.f, 0.f);
        const int n1 = BN * 16;
        const int n2 = BN * 3 / 4;
        for (int i = t0; i < n1 + n2; i += 256 * 256) {
            if (i < n1) ((float4*)g_dh)[i] = z;
            else        ((float4*)g_dx)[i - n1] = z;
        }
        return;
    }

    const int tid  = threadIdx.x;
    const int lane = tid & 31, warp = tid >> 5;
    const int wm = warp & 3, wn = warp >> 2;
    const int gq = lane >> 2, tq = lane & 3;
    const int m0 = blockIdx.x * 128;
    const uint32_t smem_u32 = (uint32_t)__cvta_generic_to_shared(sm);

    float acc[2][8][4];
#pragma unroll
    for (int i = 0; i < 2; i++)
#pragma unroll
        for (int j = 0; j < 8; j++)
#pragma unroll
            for (int q = 0; q < 4; q++) acc[i][j][q] = 0.f;

    auto cpA = [&](int chunk, int p) {
        const float* src = g_Ah + ((size_t)chunk * BN + m0) * 16;
#pragma unroll
        for (int it = 0; it < 2; it++) {
            const int q = tid + it * 256;        // 0..511
            const int row = q >> 2, seg = q & 3;
            cp_async16(smem_u32 + (p * BUFW + row * 24 + seg * 4) * 4,
                       src + row * 16 + seg * 4);
        }
    };
    auto cpB = [&](int chunk, int p) {
        const float* src = g_Bp + (size_t)chunk * 3072;
        const uint32_t dst = smem_u32 + (p * BUFW + 3072) * 4;
#pragma unroll
        for (int it = 0; it < 3; it++) {
            const int q = tid + it * 256;
            cp_async16(dst + q * 16, src + q * 4);
        }
        asm volatile("cp.async.commit_group;" ::: "memory");
    };
    auto compute = [&](int p) {
        const uint32_t* bA = (const uint32_t*)(sm + p * BUFW);
        const uint32_t* bB = (const uint32_t*)(sm + p * BUFW + 3072);
#pragma unroll
        for (int g = 0; g < 2; g++) {
            uint32_t af[2][4], bf[8][2];
#pragma unroll
            for (int i = 0; i < 2; i++) {
                const int r = wm * 32 + i * 16 + gq;
                const uint2 lo = *(const uint2*)&bA[r * 24 + g * 8 + 2 * tq];
                const uint2 hi = *(const uint2*)&bA[(r + 8) * 24 + g * 8 + 2 * tq];
                af[i][0] = lo.x; af[i][1] = hi.x; af[i][2] = lo.y; af[i][3] = hi.y;
            }
#pragma unroll
            for (int j = 0; j < 8; j++) {
                const int c = wn * 64 + j * 8 + gq;
                const uint2 b = *(const uint2*)&bB[c * 24 + g * 8 + 2 * tq];
                bf[j][0] = b.x; bf[j][1] = b.y;
            }
#pragma unroll
            for (int i = 0; i < 2; i++)
#pragma unroll
                for (int j = 0; j < 8; j++)
                    mma_bf16(acc[i][j], af[i], bf[j]);
        }
    };

    cpA(0, 0); cpB(0, 0);
    asm volatile("cp.async.wait_group 0;" ::: "memory");
    __syncthreads();
    for (int c = 0; c < 4; c++) {
        if (c + 1 < 4) { cpA(c + 1, (c + 1) & 1); cpB(c + 1, (c + 1) & 1); }
        compute(c & 1);
        if (c + 1 < 4) {
            asm volatile("cp.async.wait_group 0;" ::: "memory");
            __syncthreads();
        }
    }

#pragma unroll
    for (int i = 0; i < 2; i++)
#pragma unroll
        for (int h2 = 0; h2 < 2; h2++) {
            const int r = m0 + wm * 32 + i * 16 + gq + h2 * 8;
#pragma unroll
            for (int j = 0; j < 8; j++) {
                const int c = wn * 64 + j * 8 + tq * 2;
                *(float2*)(g_P + (size_t)r * 128 + c) =
                    make_float2(acc[i][j][h2 * 2 + 0], acc[i][j][h2 * 2 + 1]);
            }
        }
}

// ===== fused node MLP (bf16), 64-row CTA, 3 CTAs/SM, cp.async A ============
// words: B0 @0, B1 @3072, A_p @6144+p*1536, tT @6144 [64][72] (overlays A)
__global__ __launch_bounds__(256, 3) void gemm_fused(
    const float* __restrict__ A,
    const float* __restrict__ b1,
    const float* __restrict__ b2,
    float* __restrict__ OutH,
    const float* __restrict__ X,
    float* __restrict__ OutX)
{
    extern __shared__ float sm[];
    __shared__ float sB1s[128], sB2s[128];

    if (blockIdx.x >= 1024) {
        const int t0 = (blockIdx.x - 1024) * 256 + threadIdx.x;
        for (int i = t0; i < BN * 3; i += 256 * 256)
            OutX[i] = X[i] + g_dx[i];
        return;
    }

    const int tid  = threadIdx.x;
    const int lane = tid & 31, warp = tid >> 5;
    const int wm = warp & 3, wn = warp >> 2;      // rows wm*16, cols wn*64
    const int gq = lane >> 2, tq = lane & 3;
    const int m0 = blockIdx.x * 64;
    const uint32_t smem_u32 = (uint32_t)__cvta_generic_to_shared(sm);
    uint32_t* tT = (uint32_t*)(sm + 6144);        // [64][72]

    if (tid < 128) sB1s[tid] = b1[tid];
    else           sB2s[tid - 128] = b2[tid - 128];

    // dh-chunk staging (chunks 4,5 only)
    float4 ra[2];
    const int arow = tid >> 2;
    const int ag   = (tid >> 1) & 1;
    const int ah   = tid & 1;

    auto ldg_dh = [&](int dh0) {                  // dh0 = 0 (chunk4) or 32 (chunk5)
        const float* src = g_dh + (size_t)(m0 + arow) * 64 + dh0 + ag * 16 + ah * 8;
        ra[0] = *(const float4*)(src);
        ra[1] = *(const float4*)(src + 4);
    };
    auto sts_dh = [&](int p) {
        uint32_t* bA = (uint32_t*)(sm + 6144 + p * 1536);
        uint32_t* d = &bA[arow * 24 + ag * 8 + ah];
        d[0] = pack_bf16(ra[0].x, ra[0].y);
        d[2] = pack_bf16(ra[0].z, ra[0].w);
        d[4] = pack_bf16(ra[1].x, ra[1].y);
        d[6] = pack_bf16(ra[1].z, ra[1].w);
    };
    auto cpA = [&](int chunk, int p) {            // chunks 0..3 from g_Ah
        const int row = tid >> 2, seg = tid & 3;
        cp_async16(smem_u32 + (6144 + p * 1536 + row * 24 + seg * 4) * 4,
                   g_Ah + ((size_t)chunk * BN + m0 + row) * 16 + seg * 4);
    };
    auto cpB = [&](int chunk, int p) {
        const float* src = g_Bp + (size_t)chunk * 3072;
        const uint32_t dst = smem_u32 + (p * 3072) * 4;
#pragma unroll
        for (int it = 0; it < 3; it++) {
            const int q = tid + it * 256;
            cp_async16(dst + q * 16, src + q * 4);
        }
        asm volatile("cp.async.commit_group;" ::: "memory");
    };

    // ---------------- phase 1: t = silu([h|dh]@W1 + b1) ----------------
    {
        float acc[8][4];
#pragma unroll
        for (int j = 0; j < 8; j++)
#pragma unroll
            for (int q = 0; q < 4; q++) acc[j][q] = 0.f;

        auto compute = [&](int p) {
            const uint32_t* bA = (const uint32_t*)(sm + 6144 + p * 1536);
            const uint32_t* bB = (const uint32_t*)(sm + p * 3072);
#pragma unroll
            for (int g = 0; g < 2; g++) {
                uint32_t af[4], bf[8][2];
                const int r = wm * 16 + gq;
                const uint2 lo = *(const uint2*)&bA[r * 24 + g * 8 + 2 * tq];
                const uint2 hi = *(const uint2*)&bA[(r + 8) * 24 + g * 8 + 2 * tq];
                af[0] = lo.x; af[1] = hi.x; af[2] = lo.y; af[3] = hi.y;
#pragma unroll
                for (int j = 0; j < 8; j++) {
                    const int c = wn * 64 + j * 8 + gq;
                    const uint2 b = *(const uint2*)&bB[c * 24 + g * 8 + 2 * tq];
                    bf[j][0] = b.x; bf[j][1] = b.y;
                }
#pragma unroll
                for (int j = 0; j < 8; j++)
                    mma_bf16(acc[j], af, bf[j]);
            }
        };

        cpA(0, 0); cpB(4, 0);
        asm volatile("cp.async.wait_group 0;" ::: "memory");
        __syncthreads();
        for (int c = 0; c < 6; c++) {
            if (c + 1 < 6) {
                if (c + 1 <= 3) cpA(c + 1, (c + 1) & 1);
                cpB(5 + c, (c + 1) & 1);
            }
            if (c == 2) ldg_dh(0);                      // chunk 4 data
            if (c == 3) { sts_dh(0); ldg_dh(32); }      // store c4 -> buf0, load c5
            if (c == 4) sts_dh(1);                      // store c5 -> buf1
            if (c == 5) cpB(10, 0);                     // phase-2 prefetch
            compute(c & 1);
            if (c + 1 < 6) {
                asm volatile("cp.async.wait_group 0;" ::: "memory");
                __syncthreads();
            } else {
                __syncthreads();
            }
        }

        // epilogue 1: silu(+b1) -> tT bf16x2
#pragma unroll
        for (int h2 = 0; h2 < 2; h2++) {
            const int rl = wm * 16 + gq + h2 * 8;
#pragma unroll
            for (int j = 0; j < 8; j++) {
                const int c = wn * 64 + j * 8 + tq * 2;
                const float v0 = silu_f(acc[j][h2 * 2 + 0] + sB1s[c]);
                const float v1 = silu_f(acc[j][h2 * 2 + 1] + sB1s[c + 1]);
                tT[rl * 72 + (wn * 4 + (j >> 1)) * 8 + tq * 2 + (j & 1)] =
                    pack_bf16(v0, v1);
            }
        }
    }

    // ---------------- phase 2: out = h + t@W2 + b2 ----------------
    {
        float acc[8][4];
#pragma unroll
        for (int j = 0; j < 8; j++)
#pragma unroll
            for (int q = 0; q < 4; q++) acc[j][q] = 0.f;

        cpB(11, 1);
        asm volatile("cp.async.wait_group 1;" ::: "memory");  // chunk 10 ready
        __syncthreads();                                       // + tT visible

        for (int kc = 0; kc < 4; kc++) {
            const uint32_t* bB = (const uint32_t*)(sm + (kc & 1) * 3072);
#pragma unroll
            for (int ks = 0; ks < 2; ks++) {
                const int kg = kc * 2 + ks;       // k16-group over K=128
                uint32_t af[4], bf[8][2];
                const int r = wm * 16 + gq;
                const uint2 lo = *(const uint2*)&tT[r * 72 + kg * 8 + 2 * tq];
                const uint2 hi = *(const uint2*)&tT[(r + 8) * 72 + kg * 8 + 2 * tq];
                af[0] = lo.x; af[1] = hi.x; af[2] = lo.y; af[3] = hi.y;
#pragma unroll
                for (int j = 0; j < 8; j++) {
                    const int c = wn * 64 + j * 8 + gq;
                    const uint2 b = *(const uint2*)&bB[c * 24 + ks * 8 + 2 * tq];
                    bf[j][0] = b.x; bf[j][1] = b.y;
                }
#pragma unroll
                for (int j = 0; j < 8; j++)
                    mma_bf16(acc[j], af, bf[j]);
            }
            if (kc < 3) {
                asm volatile("cp.async.wait_group 0;" ::: "memory");
                __syncthreads();
                if (kc + 2 < 4) cpB(12 + kc, kc & 1);
            }
        }

#pragma unroll
        for (int h2 = 0; h2 < 2; h2++) {
            const int r = m0 + wm * 16 + gq + h2 * 8;
#pragma unroll
            for (int j = 0; j < 8; j++) {
                const int c = wn * 64 + j * 8 + tq * 2;
                const size_t base = (size_t)r * 128 + c;
                const float2 hh = *(const float2*)(A + base);
                const float v0 = acc[j][h2 * 2 + 0] + sB2s[c] + hh.x;
                const float v1 = acc[j][h2 * 2 + 1] + sB2s[c + 1] + hh.y;
                *(float2*)(OutH + base) = make_float2(v0, v1);
            }
        }
    }
}

// -------- edge kernel (bf16): 128 edges/block, 256 threads, 4 CTAs/SM -------
__global__ __launch_bounds__(256, 4) void edge_kernel(
    const float* __restrict__ x,
    const int*   __restrict__ edges,
    const float* __restrict__ W1,
    const float* __restrict__ b1,
    const float* __restrict__ b2,
    const float* __restrict__ pxw)
{
    extern __shared__ float dyn[];
    uint32_t* sW2 = (uint32_t*)dyn;            // [64 n][40]
    uint32_t* sM  = (uint32_t*)(dyn + 2560);   // [128 e][40]

    __shared__ int   sSrc[EPB], sDst[EPB];
    __shared__ float sD2[EPB];
    __shared__ float sDirx[EPB], sDiry[EPB], sDirz[EPB];
    __shared__ float sB1[64], sB2[64], sPx[64], sW1r[64];

    const int tid  = threadIdx.x;
    const int lane = tid & 31, warp = tid >> 5;
    const int gq = lane >> 2, tq = lane & 3;
    const int e0 = blockIdx.x * EPB;

    if (tid < EPB) {
        const int eg = e0 + tid;
        const int b  = eg >> 16;
        const int2 sd = ((const int2*)edges)[eg];
        const int gi = b * NPB + sd.x;
        const int gj = b * NPB + sd.y;
        sSrc[tid] = gi; sDst[tid] = gj;
        const float xi0 = x[(size_t)gi * 3 + 0], xi1 = x[(size_t)gi * 3 + 1], xi2 = x[(size_t)gi * 3 + 2];
        const float xj0 = x[(size_t)gj * 3 + 0], xj1 = x[(size_t)gj * 3 + 1], xj2 = x[(size_t)gj * 3 + 2];
        const float d0 = xi0 - xj0, d1 = xi1 - xj1, d2c = xi2 - xj2;
        float d2 = d0 * d0 + d1 * d1 + d2c * d2c;
        d2 = fmaxf(d2, 1e-12f);
        sD2[tid] = d2;
        const float inv = 1.0f / (sqrtf(d2) + 1e-8f);
        sDirx[tid] = d0 * inv; sDiry[tid] = d1 * inv; sDirz[tid] = d2c * inv;
    }
    if (tid >= 128 && tid < 192) {
        const int t = tid - 128;
        sB1[t] = b1[t];
        sB2[t] = b2[t];
        sPx[t] = pxw[t];
        sW1r[t] = W1[256 * 64 + t];
    }
#pragma unroll
    for (int it = 0; it < 3; it++) {
        const int q = tid + it * 256;
        if (q < 640) *(uint4*)&sW2[q * 4] = *(const uint4*)&g_W2p[q * 4];
    }
    __syncthreads();

#pragma unroll
    for (int it = 0; it < 8; ++it) {
        const int idx = it * 256 + tid;
        const int e = idx >> 4, q = idx & 15;
        const int k = q * 4;
        const float4 a = __ldg((const float4*)(g_P + (size_t)sSrc[e] * 128 + k));
        const float4 b = __ldg((const float4*)(g_P + (size_t)sDst[e] * 128 + 64 + k));
        const float4 wv = *(const float4*)&sW1r[k];
        const float4 bv = *(const float4*)&sB1[k];
        const float d2 = sD2[e];
        const float v0 = silu_f(a.x + b.x + d2 * wv.x + bv.x);
        const float v1 = silu_f(a.y + b.y + d2 * wv.y + bv.y);
        const float v2 = silu_f(a.z + b.z + d2 * wv.z + bv.z);
        const float v3 = silu_f(a.w + b.w + d2 * wv.w + bv.w);
        const int g = q >> 2, qm = q & 3;
        const int s0 = (qm & 1) * 4 + (qm >> 1);
        uint32_t* dst = &sM[e * 40 + g * 8];
        dst[s0]     = pack_bf16(v0, v1);
        dst[s0 + 2] = pack_bf16(v2, v3);
    }
    __syncthreads();

    float acc[8][4];
#pragma unroll
    for (int j = 0; j < 8; j++)
#pragma unroll
        for (int q = 0; q < 4; q++) acc[j][q] = 0.f;

#pragma unroll
    for (int g = 0; g < 4; g++) {
        uint32_t af[4], bf[2];
        const int r = warp * 16 + gq;
        const uint2 lo = *(const uint2*)&sM[r * 40 + g * 8 + 2 * tq];
        const uint2 hi = *(const uint2*)&sM[(r + 8) * 40 + g * 8 + 2 * tq];
        af[0] = lo.x; af[1] = hi.x; af[2] = lo.y; af[3] = hi.y;
#pragma unroll
        for (int j = 0; j < 8; j++) {
            const int c = j * 8 + gq;
            const uint2 b = *(const uint2*)&sW2[c * 40 + g * 8 + 2 * tq];
            bf[0] = b.x; bf[1] = b.y;
            mma_bf16(acc[j], af, bf);
        }
    }

    const int r0 = warp * 16 + gq;
    const int n0 = sSrc[r0], n1 = sSrc[r0 + 8];
    float part0 = 0.f, part1 = 0.f;
#pragma unroll
    for (int j = 0; j < 8; j++) {
        const int c = j * 8 + tq * 2;
        const float bb0 = sB2[c], bb1 = sB2[c + 1];
        const float px0 = sPx[c], px1 = sPx[c + 1];
        const float v0 = silu_f(acc[j][0] + bb0);
        const float v1 = silu_f(acc[j][1] + bb1);
        const float v2 = silu_f(acc[j][2] + bb0);
        const float v3 = silu_f(acc[j][3] + bb1);
        part0 += v0 * px0 + v1 * px1;
        part1 += v2 * px0 + v3 * px1;
        red_add_v2(g_dh + (size_t)n0 * 64 + c, v0, v1);
        red_add_v2(g_dh + (size_t)n1 * 64 + c, v2, v3);
    }
    part0 += __shfl_xor_sync(0xffffffffu, part0, 1);
    part0 += __shfl_xor_sync(0xffffffffu, part0, 2);
    part1 += __shfl_xor_sync(0xffffffffu, part1, 1);
    part1 += __shfl_xor_sync(0xffffffffu, part1, 2);
    if (tq == 0) {
        atomicAdd(&g_dx[(size_t)n0 * 3 + 0], part0 * sDirx[r0]);
        atomicAdd(&g_dx[(size_t)n0 * 3 + 1], part0 * sDiry[r0]);
        atomicAdd(&g_dx[(size_t)n0 * 3 + 2], part0 * sDirz[r0]);
        atomicAdd(&g_dx[(size_t)n1 * 3 + 0], part1 * sDirx[r0 + 8]);
        atomicAdd(&g_dx[(size_t)n1 * 3 + 1], part1 * sDiry[r0 + 8]);
        atomicAdd(&g_dx[(size_t)n1 * 3 + 2], part1 * sDirz[r0 + 8]);
    }
}

// ---------------- launch ----------------
extern "C" void kernel_launch(void* const* d_in, const int* in_sizes, int n_in,
                              void* d_out, int out_size) {
    const float* x   = (const float*)d_in[0];
    const float* h   = (const float*)d_in[1];
    const int*   ei  = (const int*)d_in[2];
    const float* pw1 = (const float*)d_in[3];
    const float* pb1 = (const float*)d_in[4];
    const float* pw2 = (const float*)d_in[5];
    const float* pb2 = (const float*)d_in[6];
    const float* pxw = (const float*)d_in[7];
    const float* hw1 = (const float*)d_in[8];
    const float* hb1 = (const float*)d_in[9];
    const float* hw2 = (const float*)d_in[10];
    const float* hb2 = (const float*)d_in[11];

    float* out   = (float*)d_out;
    float* out_x = out;
    float* out_h = out + (size_t)BN * 3;

    const int GSMEM = 2 * 6144 * (int)sizeof(float);                   // 49152 B
    const int FSMEM = (6144 + 64 * 72) * (int)sizeof(float);           // 43008 B
    const int EDGE_SMEM = (2560 + 128 * 40) * (int)sizeof(float);      // 30720 B
    cudaFuncSetAttribute(gemm_p, cudaFuncAttributeMaxDynamicSharedMemorySize, GSMEM);
    cudaFuncSetAttribute(gemm_fused, cudaFuncAttributeMaxDynamicSharedMemorySize, FSMEM);
    cudaFuncSetAttribute(edge_kernel, cudaFuncAttributeMaxDynamicSharedMemorySize, EDGE_SMEM);

    prep_kernel<<<512, 256>>>(pw1, hw1, hw2, pw2, h);
    gemm_p<<<512 + 256, 256, GSMEM>>>();
    edge_kernel<<<NE / EPB, 256, EDGE_SMEM>>>(x, ei, pw1, pb1, pb2, pxw);
    gemm_fused<<<BN / 64 + 256, 256, FSMEM>>>(h, hb1, hb2, out_h, x, out_x);
}

// round 16
// speedup vs baseline: 1.0539x; 1.0539x over previous
#include <cuda_runtime.h>
#include <cuda_fp16.h>
#include <math.h>
#include <stdint.h>

#define BN   65536
#define NPB  16384
#define NE   262144
#define EPB  128

// g_Bp: 14 K32-chunks x 128 n x 24 words (bf16x2 pairs, pair-slot interleaved)
__device__ __align__(16) float  g_P [(size_t)BN * 128];
__device__ __align__(16) __half g_dh[(size_t)BN * 64];     // f16 accumulators
__device__ __align__(16) float  g_dx[(size_t)BN * 3];
__device__ __align__(16) float  g_Bp[14 * 128 * 24];
__device__ __align__(16) float  g_W2p[64 * 40];

__device__ __forceinline__ float silu_f(float v) {
    return v * (1.0f / (1.0f + __expf(-v)));
}
__device__ __forceinline__ uint32_t pack_bf16(float lo, float hi) {
    uint32_t r;
    asm("cvt.rn.bf16x2.f32 %0, %1, %2;" : "=r"(r) : "f"(hi), "f"(lo));
    return r;
}
__device__ __forceinline__ void mma_bf16(float* c, const uint32_t* a, const uint32_t* b) {
    asm volatile("mma.sync.aligned.m16n8k16.row.col.f32.bf16.bf16.f32 "
        "{%0,%1,%2,%3}, {%4,%5,%6,%7}, {%8,%9}, {%0,%1,%2,%3};"
        : "+f"(c[0]), "+f"(c[1]), "+f"(c[2]), "+f"(c[3])
        : "r"(a[0]), "r"(a[1]), "r"(a[2]), "r"(a[3]), "r"(b[0]), "r"(b[1]));
}
__device__ __forceinline__ void red_add_h2(__half* p, float a, float b) {
    __half2 v = __floats2half2_rn(a, b);
    asm volatile("red.global.add.noftz.f16x2 [%0], %1;"
                 :: "l"(p), "r"(*(uint32_t*)&v) : "memory");
}
__device__ __forceinline__ void cp_async16(uint32_t dst, const void* src) {
    asm volatile("cp.async.cg.shared.global [%0], [%1], 16;" :: "r"(dst), "l"(src));
}

// ---------------- prep: weights -> bf16x2 pair-interleaved ------------------
__global__ void prep_kernel(const float* __restrict__ pw1,
                            const float* __restrict__ hw1,
                            const float* __restrict__ hw2,
                            const float* __restrict__ pw2)
{
    const int stride = gridDim.x * blockDim.x;
    const int idx0 = blockIdx.x * blockDim.x + threadIdx.x;
    for (int i = idx0; i < 14 * 128 * 24; i += stride) {
        const int w = i % 24, n = (i / 24) & 127, c = i / (24 * 128);
        float v = 0.f;
        if (w < 16) {
            const int g = w >> 3, s = w & 7;
            const int p = (s >> 1) + ((s & 1) << 2);
            const int kl = 16 * g + 2 * p;
            float lo, hi;
            if (c < 4) {
                const int k = c * 32 + kl;
                if (n < 64) { lo = pw1[k * 64 + n];         hi = pw1[(k + 1) * 64 + n]; }
                else        { lo = pw1[(128 + k) * 64 + (n - 64)];
                              hi = pw1[(129 + k) * 64 + (n - 64)]; }
            } else if (c < 10) {
                const int k = (c - 4) * 32 + kl;
                lo = hw1[k * 128 + n]; hi = hw1[(k + 1) * 128 + n];
            } else {
                const int k = (c - 10) * 32 + kl;
                lo = hw2[k * 128 + n]; hi = hw2[(k + 1) * 128 + n];
            }
            v = __uint_as_float(pack_bf16(lo, hi));
        }
        g_Bp[i] = v;
    }
    for (int i = idx0; i < 64 * 40; i += stride) {
        const int w = i % 40, n = i / 40;
        float v = 0.f;
        if (w < 32) {
            const int g = w >> 3, s = w & 7;
            const int p = (s >> 1) + ((s & 1) << 2);
            const int k = 16 * g + 2 * p;
            v = __uint_as_float(pack_bf16(pw2[k * 64 + n], pw2[(k + 1) * 64 + n]));
        }
        g_W2p[i] = v;
    }
}

// ============ gemm_p: bf16 CTA 128x128, warp 32x64 + zero tail ==============
__global__ __launch_bounds__(256, 2) void gemm_p(const float* __restrict__ A)
{
    extern __shared__ float sm[];
    const int BUFW = 6144;

    if (blockIdx.x >= 512) {          // zero g_dh (f16) / g_dx (overlaps P compute)
        const int t0 = (blockIdx.x - 512) * 256 + threadIdx.x;
        uint4  zi = make_uint4(0u, 0u, 0u, 0u);
        float4 zf = make_float4(0.f, 0.f, 0.f, 0.f);
        const int n1 = BN * 8;                 // g_dh: BN*64 halves / 8 per uint4
        const int n2 = BN * 3 / 4;
        for (int i = t0; i < n1 + n2; i += 256 * 256) {
            if (i < n1) ((uint4*)g_dh)[i] = zi;
            else        ((float4*)g_dx)[i - n1] = zf;
        }
        return;
    }

    const int tid  = threadIdx.x;
    const int lane = tid & 31, warp = tid >> 5;
    const int wm = warp & 3, wn = warp >> 2;
    const int gq = lane >> 2, tq = lane & 3;
    const int m0 = blockIdx.x * 128;
    const uint32_t smem_u32 = (uint32_t)__cvta_generic_to_shared(sm);

    float acc[2][8][4];
#pragma unroll
    for (int i = 0; i < 2; i++)
#pragma unroll
        for (int j = 0; j < 8; j++)
#pragma unroll
            for (int q = 0; q < 4; q++) acc[i][j][q] = 0.f;

    float4 ra[4];
    const int am = tid >> 1;
    const int ag = tid & 1;

    auto ldgA = [&](int k0) {
        const float* src = A + (size_t)(m0 + am) * 128 + k0 + ag * 16;
        ra[0] = *(const float4*)(src);
        ra[1] = *(const float4*)(src + 4);
        ra[2] = *(const float4*)(src + 8);
        ra[3] = *(const float4*)(src + 12);
    };
    auto stsA = [&](int p) {
        uint32_t w[8];
        w[0] = pack_bf16(ra[0].x, ra[0].y); w[2] = pack_bf16(ra[0].z, ra[0].w);
        w[4] = pack_bf16(ra[1].x, ra[1].y); w[6] = pack_bf16(ra[1].z, ra[1].w);
        w[1] = pack_bf16(ra[2].x, ra[2].y); w[3] = pack_bf16(ra[2].z, ra[2].w);
        w[5] = pack_bf16(ra[3].x, ra[3].y); w[7] = pack_bf16(ra[3].z, ra[3].w);
        uint32_t* bA = (uint32_t*)(sm + p * BUFW);
        *(uint4*)&bA[am * 24 + ag * 8]     = make_uint4(w[0], w[1], w[2], w[3]);
        *(uint4*)&bA[am * 24 + ag * 8 + 4] = make_uint4(w[4], w[5], w[6], w[7]);
    };
    auto cpB = [&](int chunk, int p) {
        const float* src = g_Bp + (size_t)chunk * 3072;
        const uint32_t dst = smem_u32 + (p * BUFW + 3072) * 4;
#pragma unroll
        for (int it = 0; it < 3; it++) {
            const int q = tid + it * 256;
            cp_async16(dst + q * 16, src + q * 4);
        }
        asm volatile("cp.async.commit_group;" ::: "memory");
    };
    auto compute = [&](int p) {
        const uint32_t* bA = (const uint32_t*)(sm + p * BUFW);
        const uint32_t* bB = (const uint32_t*)(sm + p * BUFW + 3072);
#pragma unroll
        for (int g = 0; g < 2; g++) {
            uint32_t af[2][4], bf[8][2];
#pragma unroll
            for (int i = 0; i < 2; i++) {
                const int r = wm * 32 + i * 16 + gq;
                const uint2 lo = *(const uint2*)&bA[r * 24 + g * 8 + 2 * tq];
                const uint2 hi = *(const uint2*)&bA[(r + 8) * 24 + g * 8 + 2 * tq];
                af[i][0] = lo.x; af[i][1] = hi.x; af[i][2] = lo.y; af[i][3] = hi.y;
            }
#pragma unroll
            for (int j = 0; j < 8; j++) {
                const int c = wn * 64 + j * 8 + gq;
                const uint2 b = *(const uint2*)&bB[c * 24 + g * 8 + 2 * tq];
                bf[j][0] = b.x; bf[j][1] = b.y;
            }
#pragma unroll
            for (int i = 0; i < 2; i++)
#pragma unroll
                for (int j = 0; j < 8; j++)
                    mma_bf16(acc[i][j], af[i], bf[j]);
        }
    };

    ldgA(0); cpB(0, 0); stsA(0);
    asm volatile("cp.async.wait_group 0;" ::: "memory");
    __syncthreads();
    for (int c = 0; c < 4; c++) {
        if (c + 1 < 4) { ldgA((c + 1) * 32); cpB(c + 1, (c + 1) & 1); }
        compute(c & 1);
        if (c + 1 < 4) {
            stsA((c + 1) & 1);
            asm volatile("cp.async.wait_group 0;" ::: "memory");
            __syncthreads();
        }
    }

#pragma unroll
    for (int i = 0; i < 2; i++)
#pragma unroll
        for (int h2 = 0; h2 < 2; h2++) {
            const int r = m0 + wm * 32 + i * 16 + gq + h2 * 8;
#pragma unroll
            for (int j = 0; j < 8; j++) {
                const int c = wn * 64 + j * 8 + tq * 2;
                *(float2*)(g_P + (size_t)r * 128 + c) =
                    make_float2(acc[i][j][h2 * 2 + 0], acc[i][j][h2 * 2 + 1]);
            }
        }
}

// ===== fused node MLP (bf16), 64-row CTA, 3 CTAs/SM ==========================
// words: B0 @0, B1 @3072, A_p @6144+p*1536, tT @6144 [64][72] (overlays A)
__global__ __launch_bounds__(256, 3) void gemm_fused(
    const float* __restrict__ A,
    const float* __restrict__ b1,
    const float* __restrict__ b2,
    float* __restrict__ OutH,
    const float* __restrict__ X,
    float* __restrict__ OutX)
{
    extern __shared__ float sm[];
    __shared__ float sB1s[128], sB2s[128];

    if (blockIdx.x >= 1024) {
        const int t0 = (blockIdx.x - 1024) * 256 + threadIdx.x;
        for (int i = t0; i < BN * 3; i += 256 * 256)
            OutX[i] = X[i] + g_dx[i];
        return;
    }

    const int tid  = threadIdx.x;
    const int lane = tid & 31, warp = tid >> 5;
    const int wm = warp & 3, wn = warp >> 2;      // rows wm*16, cols wn*64
    const int gq = lane >> 2, tq = lane & 3;
    const int m0 = blockIdx.x * 64;
    const uint32_t smem_u32 = (uint32_t)__cvta_generic_to_shared(sm);
    uint32_t* tT = (uint32_t*)(sm + 6144);        // [64][72]

    if (tid < 128) sB1s[tid] = b1[tid];
    else           sB2s[tid - 128] = b2[tid - 128];

    float4 ra[2];
    uint4  rdh;
    const int arow = tid >> 2;
    const int ag   = (tid >> 1) & 1;
    const int ah   = tid & 1;

    auto ldgA = [&](int kc0) {
        const int f = kc0 + ag * 16 + ah * 8;
        if (f < 128) {
            const float* src = A + (size_t)(m0 + arow) * 128 + f;
            ra[0] = *(const float4*)(src);
            ra[1] = *(const float4*)(src + 4);
        } else {
            rdh = *(const uint4*)(g_dh + (size_t)(m0 + arow) * 64 + (f - 128));
        }
    };
    auto stsA = [&](int p, bool isdh) {
        uint32_t* bA = (uint32_t*)(sm + 6144 + p * 1536);
        uint32_t* d = &bA[arow * 24 + ag * 8 + ah];
        if (!isdh) {
            d[0] = pack_bf16(ra[0].x, ra[0].y);
            d[2] = pack_bf16(ra[0].z, ra[0].w);
            d[4] = pack_bf16(ra[1].x, ra[1].y);
            d[6] = pack_bf16(ra[1].z, ra[1].w);
        } else {
            const float2 f0 = __half22float2(*(const __half2*)&rdh.x);
            const float2 f1 = __half22float2(*(const __half2*)&rdh.y);
            const float2 f2 = __half22float2(*(const __half2*)&rdh.z);
            const float2 f3 = __half22float2(*(const __half2*)&rdh.w);
            d[0] = pack_bf16(f0.x, f0.y);
            d[2] = pack_bf16(f1.x, f1.y);
            d[4] = pack_bf16(f2.x, f2.y);
            d[6] = pack_bf16(f3.x, f3.y);
        }
    };
    auto cpB = [&](int chunk, int p) {
        const float* src = g_Bp + (size_t)chunk * 3072;
        const uint32_t dst = smem_u32 + (p * 3072) * 4;
#pragma unroll
        for (int it = 0; it < 3; it++) {
            const int q = tid + it * 256;
            cp_async16(dst + q * 16, src + q * 4);
        }
        asm volatile("cp.async.commit_group;" ::: "memory");
    };

    // ---------------- phase 1: t = silu([h|dh]@W1 + b1) ----------------
    {
        float acc[8][4];
#pragma unroll
        for (int j = 0; j < 8; j++)
#pragma unroll
            for (int q = 0; q < 4; q++) acc[j][q] = 0.f;

        auto compute = [&](int p) {
            const uint32_t* bA = (const uint32_t*)(sm + 6144 + p * 1536);
            const uint32_t* bB = (const uint32_t*)(sm + p * 3072);
#pragma unroll
            for (int g = 0; g < 2; g++) {
                uint32_t af[4], bf[8][2];
                const int r = wm * 16 + gq;
                const uint2 lo = *(const uint2*)&bA[r * 24 + g * 8 + 2 * tq];
                const uint2 hi = *(const uint2*)&bA[(r + 8) * 24 + g * 8 + 2 * tq];
                af[0] = lo.x; af[1] = hi.x; af[2] = lo.y; af[3] = hi.y;
#pragma unroll
                for (int j = 0; j < 8; j++) {
                    const int c = wn * 64 + j * 8 + gq;
                    const uint2 b = *(const uint2*)&bB[c * 24 + g * 8 + 2 * tq];
                    bf[j][0] = b.x; bf[j][1] = b.y;
                }
#pragma unroll
                for (int j = 0; j < 8; j++)
                    mma_bf16(acc[j], af, bf[j]);
            }
        };

        ldgA(0); cpB(4, 0); stsA(0, false);
        asm volatile("cp.async.wait_group 0;" ::: "memory");
        __syncthreads();
        for (int c = 0; c < 6; c++) {
            if (c + 1 < 6) { ldgA((c + 1) * 32); cpB(5 + c, (c + 1) & 1); }
            if (c == 5)    cpB(10, 0);   // prefetch phase-2 chunk into dead buf0
            compute(c & 1);
            if (c + 1 < 6) {
                stsA((c + 1) & 1, (c + 1) >= 4);
                asm volatile("cp.async.wait_group 0;" ::: "memory");
                __syncthreads();
            } else {
                __syncthreads();
            }
        }

        // epilogue 1: silu(+b1) -> tT bf16x2
#pragma unroll
        for (int h2 = 0; h2 < 2; h2++) {
            const int rl = wm * 16 + gq + h2 * 8;
#pragma unroll
            for (int j = 0; j < 8; j++) {
                const int c = wn * 64 + j * 8 + tq * 2;
                const float v0 = silu_f(acc[j][h2 * 2 + 0] + sB1s[c]);
                const float v1 = silu_f(acc[j][h2 * 2 + 1] + sB1s[c + 1]);
                tT[rl * 72 + (wn * 4 + (j >> 1)) * 8 + tq * 2 + (j & 1)] =
                    pack_bf16(v0, v1);
            }
        }
    }

    // ---------------- phase 2: out = h + t@W2 + b2 ----------------
    {
        float acc[8][4];
#pragma unroll
        for (int j = 0; j < 8; j++)
#pragma unroll
            for (int q = 0; q < 4; q++) acc[j][q] = 0.f;

        cpB(11, 1);
        asm volatile("cp.async.wait_group 1;" ::: "memory");  // chunk 10 ready
        __syncthreads();                                       // + tT visible

        for (int kc = 0; kc < 4; kc++) {
            const uint32_t* bB = (const uint32_t*)(sm + (kc & 1) * 3072);
#pragma unroll
            for (int ks = 0; ks < 2; ks++) {
                const int kg = kc * 2 + ks;       // k16-group over K=128
                uint32_t af[4], bf[8][2];
                const int r = wm * 16 + gq;
                const uint2 lo = *(const uint2*)&tT[r * 72 + kg * 8 + 2 * tq];
                const uint2 hi = *(const uint2*)&tT[(r + 8) * 72 + kg * 8 + 2 * tq];
                af[0] = lo.x; af[1] = hi.x; af[2] = lo.y; af[3] = hi.y;
#pragma unroll
                for (int j = 0; j < 8; j++) {
                    const int c = wn * 64 + j * 8 + gq;
                    const uint2 b = *(const uint2*)&bB[c * 24 + ks * 8 + 2 * tq];
                    bf[j][0] = b.x; bf[j][1] = b.y;
                }
#pragma unroll
                for (int j = 0; j < 8; j++)
                    mma_bf16(acc[j], af, bf[j]);
            }
            if (kc < 3) {
                asm volatile("cp.async.wait_group 0;" ::: "memory");
                __syncthreads();
                if (kc + 2 < 4) cpB(12 + kc, kc & 1);
            }
        }

#pragma unroll
        for (int h2 = 0; h2 < 2; h2++) {
            const int r = m0 + wm * 16 + gq + h2 * 8;
#pragma unroll
            for (int j = 0; j < 8; j++) {
                const int c = wn * 64 + j * 8 + tq * 2;
                const size_t base = (size_t)r * 128 + c;
                const float2 hh = *(const float2*)(A + base);
                const float v0 = acc[j][h2 * 2 + 0] + sB2s[c] + hh.x;
                const float v1 = acc[j][h2 * 2 + 1] + sB2s[c + 1] + hh.y;
                *(float2*)(OutH + base) = make_float2(v0, v1);
            }
        }
    }
}

// -------- edge kernel (bf16): 128 edges/block, 256 threads, 4 CTAs/SM -------
__global__ __launch_bounds__(256, 4) void edge_kernel(
    const float* __restrict__ x,
    const int*   __restrict__ edges,
    const float* __restrict__ W1,
    const float* __restrict__ b1,
    const float* __restrict__ b2,
    const float* __restrict__ pxw)
{
    extern __shared__ float dyn[];
    uint32_t* sW2 = (uint32_t*)dyn;            // [64 n][40]
    uint32_t* sM  = (uint32_t*)(dyn + 2560);   // [128 e][40]

    __shared__ int   sSrc[EPB], sDst[EPB];
    __shared__ float sD2[EPB];
    __shared__ float sDirx[EPB], sDiry[EPB], sDirz[EPB];
    __shared__ float sB1[64], sB2[64], sPx[64], sW1r[64];

    const int tid  = threadIdx.x;
    const int lane = tid & 31, warp = tid >> 5;
    const int gq = lane >> 2, tq = lane & 3;
    const int e0 = blockIdx.x * EPB;

    if (tid < EPB) {
        const int eg = e0 + tid;
        const int b  = eg >> 16;
        const int2 sd = ((const int2*)edges)[eg];
        const int gi = b * NPB + sd.x;
        const int gj = b * NPB + sd.y;
        sSrc[tid] = gi; sDst[tid] = gj;
        const float xi0 = x[(size_t)gi * 3 + 0], xi1 = x[(size_t)gi * 3 + 1], xi2 = x[(size_t)gi * 3 + 2];
        const float xj0 = x[(size_t)gj * 3 + 0], xj1 = x[(size_t)gj * 3 + 1], xj2 = x[(size_t)gj * 3 + 2];
        const float d0 = xi0 - xj0, d1 = xi1 - xj1, d2c = xi2 - xj2;
        float d2 = d0 * d0 + d1 * d1 + d2c * d2c;
        d2 = fmaxf(d2, 1e-12f);
        sD2[tid] = d2;
        const float inv = 1.0f / (sqrtf(d2) + 1e-8f);
        sDirx[tid] = d0 * inv; sDiry[tid] = d1 * inv; sDirz[tid] = d2c * inv;
    }
    if (tid >= 128 && tid < 192) {
        const int t = tid - 128;
        sB1[t] = b1[t];
        sB2[t] = b2[t];
        sPx[t] = pxw[t];
        sW1r[t] = W1[256 * 64 + t];
    }
#pragma unroll
    for (int it = 0; it < 3; it++) {
        const int q = tid + it * 256;
        if (q < 640) *(uint4*)&sW2[q * 4] = *(const uint4*)&g_W2p[q * 4];
    }
    __syncthreads();

#pragma unroll
    for (int it = 0; it < 8; ++it) {
        const int idx = it * 256 + tid;
        const int e = idx >> 4, q = idx & 15;
        const int k = q * 4;
        const float4 a = __ldg((const float4*)(g_P + (size_t)sSrc[e] * 128 + k));
        const float4 b = __ldg((const float4*)(g_P + (size_t)sDst[e] * 128 + 64 + k));
        const float4 wv = *(const float4*)&sW1r[k];
        const float4 bv = *(const float4*)&sB1[k];
        const float d2 = sD2[e];
        const float v0 = silu_f(a.x + b.x + d2 * wv.x + bv.x);
        const float v1 = silu_f(a.y + b.y + d2 * wv.y + bv.y);
        const float v2 = silu_f(a.z + b.z + d2 * wv.z + bv.z);
        const float v3 = silu_f(a.w + b.w + d2 * wv.w + bv.w);
        const int g = q >> 2, qm = q & 3;
        const int s0 = (qm & 1) * 4 + (qm >> 1);
        uint32_t* dst = &sM[e * 40 + g * 8];
        dst[s0]     = pack_bf16(v0, v1);
        dst[s0 + 2] = pack_bf16(v2, v3);
    }
    __syncthreads();

    float acc[8][4];
#pragma unroll
    for (int j = 0; j < 8; j++)
#pragma unroll
        for (int q = 0; q < 4; q++) acc[j][q] = 0.f;

#pragma unroll
    for (int g = 0; g < 4; g++) {
        uint32_t af[4], bf[2];
        const int r = warp * 16 + gq;
        const uint2 lo = *(const uint2*)&sM[r * 40 + g * 8 + 2 * tq];
        const uint2 hi = *(const uint2*)&sM[(r + 8) * 40 + g * 8 + 2 * tq];
        af[0] = lo.x; af[1] = hi.x; af[2] = lo.y; af[3] = hi.y;
#pragma unroll
        for (int j = 0; j < 8; j++) {
            const int c = j * 8 + gq;
            const uint2 b = *(const uint2*)&sW2[c * 40 + g * 8 + 2 * tq];
            bf[0] = b.x; bf[1] = b.y;
            mma_bf16(acc[j], af, bf);
        }
    }

    // epilogue: silu(+b2); dh scatter via f16x2 reductions (halved LTS work)
    const int r0 = warp * 16 + gq;
    const int n0 = sSrc[r0], n1 = sSrc[r0 + 8];
    float part0 = 0.f, part1 = 0.f;
#pragma unroll
    for (int j = 0; j < 8; j++) {
        const int c = j * 8 + tq * 2;
        const float bb0 = sB2[c], bb1 = sB2[c + 1];
        const float px0 = sPx[c], px1 = sPx[c + 1];
        const float v0 = silu_f(acc[j][0] + bb0);
        const float v1 = silu_f(acc[j][1] + bb1);
        const float v2 = silu_f(acc[j][2] + bb0);
        const float v3 = silu_f(acc[j][3] + bb1);
        part0 += v0 * px0 + v1 * px1;
        part1 += v2 * px0 + v3 * px1;
        red_add_h2(g_dh + (size_t)n0 * 64 + c, v0, v1);
        red_add_h2(g_dh + (size_t)n1 * 64 + c, v2, v3);
    }
    part0 += __shfl_xor_sync(0xffffffffu, part0, 1);
    part0 += __shfl_xor_sync(0xffffffffu, part0, 2);
    part1 += __shfl_xor_sync(0xffffffffu, part1, 1);
    part1 += __shfl_xor_sync(0xffffffffu, part1, 2);
    if (tq == 0) {
        atomicAdd(&g_dx[(size_t)n0 * 3 + 0], part0 * sDirx[r0]);
        atomicAdd(&g_dx[(size_t)n0 * 3 + 1], part0 * sDiry[r0]);
        atomicAdd(&g_dx[(size_t)n0 * 3 + 2], part0 * sDirz[r0]);
        atomicAdd(&g_dx[(size_t)n1 * 3 + 0], part1 * sDirx[r0 + 8]);
        atomicAdd(&g_dx[(size_t)n1 * 3 + 1], part1 * sDiry[r0 + 8]);
        atomicAdd(&g_dx[(size_t)n1 * 3 + 2], part1 * sDirz[r0 + 8]);
    }
}

// ---------------- launch ----------------
extern "C" void kernel_launch(void* const* d_in, const int* in_sizes, int n_in,
                              void* d_out, int out_size) {
    const float* x   = (const float*)d_in[0];
    const float* h   = (const float*)d_in[1];
    const int*   ei  = (const int*)d_in[2];
    const float* pw1 = (const float*)d_in[3];
    const float* pb1 = (const float*)d_in[4];
    const float* pw2 = (const float*)d_in[5];
    const float* pb2 = (const float*)d_in[6];
    const float* pxw = (const float*)d_in[7];
    const float* hw1 = (const float*)d_in[8];
    const float* hb1 = (const float*)d_in[9];
    const float* hw2 = (const float*)d_in[10];
    const float* hb2 = (const float*)d_in[11];

    float* out   = (float*)d_out;
    float* out_x = out;
    float* out_h = out + (size_t)BN * 3;

    const int GSMEM = 2 * 6144 * (int)sizeof(float);                   // 49152 B
    const int FSMEM = (6144 + 64 * 72) * (int)sizeof(float);           // 43008 B
    const int EDGE_SMEM = (2560 + 128 * 40) * (int)sizeof(float);      // 30720 B
    cudaFuncSetAttribute(gemm_p, cudaFuncAttributeMaxDynamicSharedMemorySize, GSMEM);
    cudaFuncSetAttribute(gemm_fused, cudaFuncAttributeMaxDynamicSharedMemorySize, FSMEM);
    cudaFuncSetAttribute(edge_kernel, cudaFuncAttributeMaxDynamicSharedMemorySize, EDGE_SMEM);

    prep_kernel<<<64, 256>>>(pw1, hw1, hw2, pw2);
    gemm_p<<<512 + 256, 256, GSMEM>>>(h);
    edge_kernel<<<NE / EPB, 256, EDGE_SMEM>>>(x, ei, pw1, pb1, pb2, pxw);
    gemm_fused<<<BN / 64 + 256, 256, FSMEM>>>(h, hb1, hb2, out_h, x, out_x);
}

// round 17
// speedup vs baseline: 1.0810x; 1.0258x over previous
#include <cuda_runtime.h>
#include <cuda_fp16.h>
#include <math.h>
#include <stdint.h>

#define BN   65536
#define NPB  16384
#define NE   262144
#define EPB  128

// g_Pb: per node 64 bf16x2 words = [P1(32w) | P2(32w)], word i = k-pair (2i,2i+1)
__device__ __align__(16) uint32_t g_Pb[(size_t)BN * 64];
__device__ __align__(16) __half   g_dh[(size_t)BN * 64];     // f16 accumulators
__device__ __align__(16) float    g_dx[(size_t)BN * 3];
__device__ __align__(16) float    g_Bp[14 * 128 * 24];
__device__ __align__(16) float    g_W2p[64 * 40];

__device__ __forceinline__ float silu_f(float v) {
    return v * (1.0f / (1.0f + __expf(-v)));
}
__device__ __forceinline__ uint32_t pack_bf16(float lo, float hi) {
    uint32_t r;
    asm("cvt.rn.bf16x2.f32 %0, %1, %2;" : "=r"(r) : "f"(hi), "f"(lo));
    return r;
}
__device__ __forceinline__ float bf_lo(uint32_t w) { return __uint_as_float(w << 16); }
__device__ __forceinline__ float bf_hi(uint32_t w) { return __uint_as_float(w & 0xffff0000u); }
__device__ __forceinline__ void mma_bf16(float* c, const uint32_t* a, const uint32_t* b) {
    asm volatile("mma.sync.aligned.m16n8k16.row.col.f32.bf16.bf16.f32 "
        "{%0,%1,%2,%3}, {%4,%5,%6,%7}, {%8,%9}, {%0,%1,%2,%3};"
        : "+f"(c[0]), "+f"(c[1]), "+f"(c[2]), "+f"(c[3])
        : "r"(a[0]), "r"(a[1]), "r"(a[2]), "r"(a[3]), "r"(b[0]), "r"(b[1]));
}
__device__ __forceinline__ void red_add_h2(__half* p, float a, float b) {
    __half2 v = __floats2half2_rn(a, b);
    asm volatile("red.global.add.noftz.f16x2 [%0], %1;"
                 :: "l"(p), "r"(*(uint32_t*)&v) : "memory");
}
__device__ __forceinline__ void cp_async16(uint32_t dst, const void* src) {
    asm volatile("cp.async.cg.shared.global [%0], [%1], 16;" :: "r"(dst), "l"(src));
}

// ---------------- prep: weights -> bf16x2 pair-interleaved ------------------
__global__ void prep_kernel(const float* __restrict__ pw1,
                            const float* __restrict__ hw1,
                            const float* __restrict__ hw2,
                            const float* __restrict__ pw2)
{
    const int stride = gridDim.x * blockDim.x;
    const int idx0 = blockIdx.x * blockDim.x + threadIdx.x;
    for (int i = idx0; i < 14 * 128 * 24; i += stride) {
        const int w = i % 24, n = (i / 24) & 127, c = i / (24 * 128);
        float v = 0.f;
        if (w < 16) {
            const int g = w >> 3, s = w & 7;
            const int p = (s >> 1) + ((s & 1) << 2);
            const int kl = 16 * g + 2 * p;
            float lo, hi;
            if (c < 4) {
                const int k = c * 32 + kl;
                if (n < 64) { lo = pw1[k * 64 + n];         hi = pw1[(k + 1) * 64 + n]; }
                else        { lo = pw1[(128 + k) * 64 + (n - 64)];
                              hi = pw1[(129 + k) * 64 + (n - 64)]; }
            } else if (c < 10) {
                const int k = (c - 4) * 32 + kl;
                lo = hw1[k * 128 + n]; hi = hw1[(k + 1) * 128 + n];
            } else {
                const int k = (c - 10) * 32 + kl;
                lo = hw2[k * 128 + n]; hi = hw2[(k + 1) * 128 + n];
            }
            v = __uint_as_float(pack_bf16(lo, hi));
        }
        g_Bp[i] = v;
    }
    for (int i = idx0; i < 64 * 40; i += stride) {
        const int w = i % 40, n = i / 40;
        float v = 0.f;
        if (w < 32) {
            const int g = w >> 3, s = w & 7;
            const int p = (s >> 1) + ((s & 1) << 2);
            const int k = 16 * g + 2 * p;
            v = __uint_as_float(pack_bf16(pw2[k * 64 + n], pw2[(k + 1) * 64 + n]));
        }
        g_W2p[i] = v;
    }
}

// ============ gemm_p: bf16 CTA 128x128, warp 32x64 + zero tail ==============
__global__ __launch_bounds__(256, 2) void gemm_p(const float* __restrict__ A)
{
    extern __shared__ float sm[];
    const int BUFW = 6144;

    if (blockIdx.x >= 512) {          // zero g_dh (f16) / g_dx (overlaps P compute)
        const int t0 = (blockIdx.x - 512) * 256 + threadIdx.x;
        uint4  zi = make_uint4(0u, 0u, 0u, 0u);
        float4 zf = make_float4(0.f, 0.f, 0.f, 0.f);
        const int n1 = BN * 8;                 // g_dh: BN*64 halves / 8 per uint4
        const int n2 = BN * 3 / 4;
        for (int i = t0; i < n1 + n2; i += 256 * 256) {
            if (i < n1) ((uint4*)g_dh)[i] = zi;
            else        ((float4*)g_dx)[i - n1] = zf;
        }
        return;
    }

    const int tid  = threadIdx.x;
    const int lane = tid & 31, warp = tid >> 5;
    const int wm = warp & 3, wn = warp >> 2;
    const int gq = lane >> 2, tq = lane & 3;
    const int m0 = blockIdx.x * 128;
    const uint32_t smem_u32 = (uint32_t)__cvta_generic_to_shared(sm);

    float acc[2][8][4];
#pragma unroll
    for (int i = 0; i < 2; i++)
#pragma unroll
        for (int j = 0; j < 8; j++)
#pragma unroll
            for (int q = 0; q < 4; q++) acc[i][j][q] = 0.f;

    float4 ra[4];
    const int am = tid >> 1;
    const int ag = tid & 1;

    auto ldgA = [&](int k0) {
        const float* src = A + (size_t)(m0 + am) * 128 + k0 + ag * 16;
        ra[0] = *(const float4*)(src);
        ra[1] = *(const float4*)(src + 4);
        ra[2] = *(const float4*)(src + 8);
        ra[3] = *(const float4*)(src + 12);
    };
    auto stsA = [&](int p) {
        uint32_t w[8];
        w[0] = pack_bf16(ra[0].x, ra[0].y); w[2] = pack_bf16(ra[0].z, ra[0].w);
        w[4] = pack_bf16(ra[1].x, ra[1].y); w[6] = pack_bf16(ra[1].z, ra[1].w);
        w[1] = pack_bf16(ra[2].x, ra[2].y); w[3] = pack_bf16(ra[2].z, ra[2].w);
        w[5] = pack_bf16(ra[3].x, ra[3].y); w[7] = pack_bf16(ra[3].z, ra[3].w);
        uint32_t* bA = (uint32_t*)(sm + p * BUFW);
        *(uint4*)&bA[am * 24 + ag * 8]     = make_uint4(w[0], w[1], w[2], w[3]);
        *(uint4*)&bA[am * 24 + ag * 8 + 4] = make_uint4(w[4], w[5], w[6], w[7]);
    };
    auto cpB = [&](int chunk, int p) {
        const float* src = g_Bp + (size_t)chunk * 3072;
        const uint32_t dst = smem_u32 + (p * BUFW + 3072) * 4;
#pragma unroll
        for (int it = 0; it < 3; it++) {
            const int q = tid + it * 256;
            cp_async16(dst + q * 16, src + q * 4);
        }
        asm volatile("cp.async.commit_group;" ::: "memory");
    };
    auto compute = [&](int p) {
        const uint32_t* bA = (const uint32_t*)(sm + p * BUFW);
        const uint32_t* bB = (const uint32_t*)(sm + p * BUFW + 3072);
#pragma unroll
        for (int g = 0; g < 2; g++) {
            uint32_t af[2][4], bf[8][2];
#pragma unroll
            for (int i = 0; i < 2; i++) {
                const int r = wm * 32 + i * 16 + gq;
                const uint2 lo = *(const uint2*)&bA[r * 24 + g * 8 + 2 * tq];
                const uint2 hi = *(const uint2*)&bA[(r + 8) * 24 + g * 8 + 2 * tq];
                af[i][0] = lo.x; af[i][1] = hi.x; af[i][2] = lo.y; af[i][3] = hi.y;
            }
#pragma unroll
            for (int j = 0; j < 8; j++) {
                const int c = wn * 64 + j * 8 + gq;
                const uint2 b = *(const uint2*)&bB[c * 24 + g * 8 + 2 * tq];
                bf[j][0] = b.x; bf[j][1] = b.y;
            }
#pragma unroll
            for (int i = 0; i < 2; i++)
#pragma unroll
                for (int j = 0; j < 8; j++)
                    mma_bf16(acc[i][j], af[i], bf[j]);
        }
    };

    ldgA(0); cpB(0, 0); stsA(0);
    asm volatile("cp.async.wait_group 0;" ::: "memory");
    __syncthreads();
    for (int c = 0; c < 4; c++) {
        if (c + 1 < 4) { ldgA((c + 1) * 32); cpB(c + 1, (c + 1) & 1); }
        compute(c & 1);
        if (c + 1 < 4) {
            stsA((c + 1) & 1);
            asm volatile("cp.async.wait_group 0;" ::: "memory");
            __syncthreads();
        }
    }

    // epilogue: pack pairs (tq*2, tq*2+1) -> bf16x2 word
#pragma unroll
    for (int i = 0; i < 2; i++)
#pragma unroll
        for (int h2 = 0; h2 < 2; h2++) {
            const int r = m0 + wm * 32 + i * 16 + gq + h2 * 8;
#pragma unroll
            for (int j = 0; j < 8; j++) {
                const int c = wn * 64 + j * 8 + tq * 2;
                g_Pb[(size_t)r * 64 + (c >> 1)] =
                    pack_bf16(acc[i][j][h2 * 2 + 0], acc[i][j][h2 * 2 + 1]);
            }
        }
}

// ===== fused node MLP (bf16), 64-row CTA, 3 CTAs/SM ==========================
// words: B0 @0, B1 @3072, A_p @6144+p*1536, tT @6144 [64][72] (overlays A)
__global__ __launch_bounds__(256, 3) void gemm_fused(
    const float* __restrict__ A,
    const float* __restrict__ b1,
    const float* __restrict__ b2,
    float* __restrict__ OutH,
    const float* __restrict__ X,
    float* __restrict__ OutX)
{
    extern __shared__ float sm[];
    __shared__ float sB1s[128], sB2s[128];

    if (blockIdx.x >= 1024) {
        const int t0 = (blockIdx.x - 1024) * 256 + threadIdx.x;
        for (int i = t0; i < BN * 3; i += 256 * 256)
            OutX[i] = X[i] + g_dx[i];
        return;
    }

    const int tid  = threadIdx.x;
    const int lane = tid & 31, warp = tid >> 5;
    const int wm = warp & 3, wn = warp >> 2;      // rows wm*16, cols wn*64
    const int gq = lane >> 2, tq = lane & 3;
    const int m0 = blockIdx.x * 64;
    const uint32_t smem_u32 = (uint32_t)__cvta_generic_to_shared(sm);
    uint32_t* tT = (uint32_t*)(sm + 6144);        // [64][72]

    if (tid < 128) sB1s[tid] = b1[tid];
    else           sB2s[tid - 128] = b2[tid - 128];

    float4 ra[2];
    uint4  rdh;
    const int arow = tid >> 2;
    const int ag   = (tid >> 1) & 1;
    const int ah   = tid & 1;

    auto ldgA = [&](int kc0) {
        const int f = kc0 + ag * 16 + ah * 8;
        if (f < 128) {
            const float* src = A + (size_t)(m0 + arow) * 128 + f;
            ra[0] = *(const float4*)(src);
            ra[1] = *(const float4*)(src + 4);
        } else {
            rdh = *(const uint4*)(g_dh + (size_t)(m0 + arow) * 64 + (f - 128));
        }
    };
    auto stsA = [&](int p, bool isdh) {
        uint32_t* bA = (uint32_t*)(sm + 6144 + p * 1536);
        uint32_t* d = &bA[arow * 24 + ag * 8 + ah];
        if (!isdh) {
            d[0] = pack_bf16(ra[0].x, ra[0].y);
            d[2] = pack_bf16(ra[0].z, ra[0].w);
            d[4] = pack_bf16(ra[1].x, ra[1].y);
            d[6] = pack_bf16(ra[1].z, ra[1].w);
        } else {
            const float2 f0 = __half22float2(*(const __half2*)&rdh.x);
            const float2 f1 = __half22float2(*(const __half2*)&rdh.y);
            const float2 f2 = __half22float2(*(const __half2*)&rdh.z);
            const float2 f3 = __half22float2(*(const __half2*)&rdh.w);
            d[0] = pack_bf16(f0.x, f0.y);
            d[2] = pack_bf16(f1.x, f1.y);
            d[4] = pack_bf16(f2.x, f2.y);
            d[6] = pack_bf16(f3.x, f3.y);
        }
    };
    auto cpB = [&](int chunk, int p) {
        const float* src = g_Bp + (size_t)chunk * 3072;
        const uint32_t dst = smem_u32 + (p * 3072) * 4;
#pragma unroll
        for (int it = 0; it < 3; it++) {
            const int q = tid + it * 256;
            cp_async16(dst + q * 16, src + q * 4);
        }
        asm volatile("cp.async.commit_group;" ::: "memory");
    };

    // ---------------- phase 1: t = silu([h|dh]@W1 + b1) ----------------
    {
        float acc[8][4];
#pragma unroll
        for (int j = 0; j < 8; j++)
#pragma unroll
            for (int q = 0; q < 4; q++) acc[j][q] = 0.f;

        auto compute = [&](int p) {
            const uint32_t* bA = (const uint32_t*)(sm + 6144 + p * 1536);
            const uint32_t* bB = (const uint32_t*)(sm + p * 3072);
#pragma unroll
            for (int g = 0; g < 2; g++) {
                uint32_t af[4], bf[8][2];
                const int r = wm * 16 + gq;
                const uint2 lo = *(const uint2*)&bA[r * 24 + g * 8 + 2 * tq];
                const uint2 hi = *(const uint2*)&bA[(r + 8) * 24 + g * 8 + 2 * tq];
                af[0] = lo.x; af[1] = hi.x; af[2] = lo.y; af[3] = hi.y;
#pragma unroll
                for (int j = 0; j < 8; j++) {
                    const int c = wn * 64 + j * 8 + gq;
                    const uint2 b = *(const uint2*)&bB[c * 24 + g * 8 + 2 * tq];
                    bf[j][0] = b.x; bf[j][1] = b.y;
                }
#pragma unroll
                for (int j = 0; j < 8; j++)
                    mma_bf16(acc[j], af, bf[j]);
            }
        };

        ldgA(0); cpB(4, 0); stsA(0, false);
        asm volatile("cp.async.wait_group 0;" ::: "memory");
        __syncthreads();
        for (int c = 0; c < 6; c++) {
            if (c + 1 < 6) { ldgA((c + 1) * 32); cpB(5 + c, (c + 1) & 1); }
            if (c == 5)    cpB(10, 0);   // prefetch phase-2 chunk into dead buf0
            compute(c & 1);
            if (c + 1 < 6) {
                stsA((c + 1) & 1, (c + 1) >= 4);
                asm volatile("cp.async.wait_group 0;" ::: "memory");
                __syncthreads();
            } else {
                __syncthreads();
            }
        }

        // epilogue 1: silu(+b1) -> tT bf16x2
#pragma unroll
        for (int h2 = 0; h2 < 2; h2++) {
            const int rl = wm * 16 + gq + h2 * 8;
#pragma unroll
            for (int j = 0; j < 8; j++) {
                const int c = wn * 64 + j * 8 + tq * 2;
                const float v0 = silu_f(acc[j][h2 * 2 + 0] + sB1s[c]);
                const float v1 = silu_f(acc[j][h2 * 2 + 1] + sB1s[c + 1]);
                tT[rl * 72 + (wn * 4 + (j >> 1)) * 8 + tq * 2 + (j & 1)] =
                    pack_bf16(v0, v1);
            }
        }
    }

    // ---------------- phase 2: out = h + t@W2 + b2 ----------------
    {
        float acc[8][4];
#pragma unroll
        for (int j = 0; j < 8; j++)
#pragma unroll
            for (int q = 0; q < 4; q++) acc[j][q] = 0.f;

        cpB(11, 1);
        asm volatile("cp.async.wait_group 1;" ::: "memory");  // chunk 10 ready
        __syncthreads();                                       // + tT visible

        for (int kc = 0; kc < 4; kc++) {
            const uint32_t* bB = (const uint32_t*)(sm + (kc & 1) * 3072);
#pragma unroll
            for (int ks = 0; ks < 2; ks++) {
                const int kg = kc * 2 + ks;       // k16-group over K=128
                uint32_t af[4], bf[8][2];
                const int r = wm * 16 + gq;
                const uint2 lo = *(const uint2*)&tT[r * 72 + kg * 8 + 2 * tq];
                const uint2 hi = *(const uint2*)&tT[(r + 8) * 72 + kg * 8 + 2 * tq];
                af[0] = lo.x; af[1] = hi.x; af[2] = lo.y; af[3] = hi.y;
#pragma unroll
                for (int j = 0; j < 8; j++) {
                    const int c = wn * 64 + j * 8 + gq;
                    const uint2 b = *(const uint2*)&bB[c * 24 + ks * 8 + 2 * tq];
                    bf[j][0] = b.x; bf[j][1] = b.y;
                }
#pragma unroll
                for (int j = 0; j < 8; j++)
                    mma_bf16(acc[j], af, bf[j]);
            }
            if (kc < 3) {
                asm volatile("cp.async.wait_group 0;" ::: "memory");
                __syncthreads();
                if (kc + 2 < 4) cpB(12 + kc, kc & 1);
            }
        }

#pragma unroll
        for (int h2 = 0; h2 < 2; h2++) {
            const int r = m0 + wm * 16 + gq + h2 * 8;
#pragma unroll
            for (int j = 0; j < 8; j++) {
                const int c = wn * 64 + j * 8 + tq * 2;
                const size_t base = (size_t)r * 128 + c;
                const float2 hh = *(const float2*)(A + base);
                const float v0 = acc[j][h2 * 2 + 0] + sB2s[c] + hh.x;
                const float v1 = acc[j][h2 * 2 + 1] + sB2s[c + 1] + hh.y;
                *(float2*)(OutH + base) = make_float2(v0, v1);
            }
        }
    }
}

// -------- edge kernel (bf16): 128 edges/block, 256 threads, 4 CTAs/SM -------
__global__ __launch_bounds__(256, 4) void edge_kernel(
    const float* __restrict__ x,
    const int*   __restrict__ edges,
    const float* __restrict__ W1,
    const float* __restrict__ b1,
    const float* __restrict__ b2,
    const float* __restrict__ pxw)
{
    extern __shared__ float dyn[];
    uint32_t* sW2 = (uint32_t*)dyn;            // [64 n][40]
    uint32_t* sM  = (uint32_t*)(dyn + 2560);   // [128 e][40]

    __shared__ int   sSrc[EPB], sDst[EPB];
    __shared__ float sD2[EPB];
    __shared__ float sDirx[EPB], sDiry[EPB], sDirz[EPB];
    __shared__ float sB1[64], sB2[64], sPx[64], sW1r[64];

    const int tid  = threadIdx.x;
    const int lane = tid & 31, warp = tid >> 5;
    const int gq = lane >> 2, tq = lane & 3;
    const int e0 = blockIdx.x * EPB;

    if (tid < EPB) {
        const int eg = e0 + tid;
        const int b  = eg >> 16;
        const int2 sd = ((const int2*)edges)[eg];
        const int gi = b * NPB + sd.x;
        const int gj = b * NPB + sd.y;
        sSrc[tid] = gi; sDst[tid] = gj;
        const float xi0 = x[(size_t)gi * 3 + 0], xi1 = x[(size_t)gi * 3 + 1], xi2 = x[(size_t)gi * 3 + 2];
        const float xj0 = x[(size_t)gj * 3 + 0], xj1 = x[(size_t)gj * 3 + 1], xj2 = x[(size_t)gj * 3 + 2];
        const float d0 = xi0 - xj0, d1 = xi1 - xj1, d2c = xi2 - xj2;
        float d2 = d0 * d0 + d1 * d1 + d2c * d2c;
        d2 = fmaxf(d2, 1e-12f);
        sD2[tid] = d2;
        const float inv = 1.0f / (sqrtf(d2) + 1e-8f);
        sDirx[tid] = d0 * inv; sDiry[tid] = d1 * inv; sDirz[tid] = d2c * inv;
    }
    if (tid >= 128 && tid < 192) {
        const int t = tid - 128;
        sB1[t] = b1[t];
        sB2[t] = b2[t];
        sPx[t] = pxw[t];
        sW1r[t] = W1[256 * 64 + t];
    }
#pragma unroll
    for (int it = 0; it < 3; it++) {
        const int q = tid + it * 256;
        if (q < 640) *(uint4*)&sW2[q * 4] = *(const uint4*)&g_W2p[q * 4];
    }
    __syncthreads();

    // gather (bf16) + silu -> sM; item = (edge e, oct q of 8), k = q*8..q*8+7
#pragma unroll
    for (int it = 0; it < 4; ++it) {
        const int idx = it * 256 + tid;
        const int e = idx >> 3, q = idx & 7;
        const uint4 aw = __ldg((const uint4*)(g_Pb + (size_t)sSrc[e] * 64 + q * 4));
        const uint4 bw = __ldg((const uint4*)(g_Pb + (size_t)sDst[e] * 64 + 32 + q * 4));
        const float4 wva = *(const float4*)&sW1r[q * 8];
        const float4 wvb = *(const float4*)&sW1r[q * 8 + 4];
        const float4 bva = *(const float4*)&sB1[q * 8];
        const float4 bvb = *(const float4*)&sB1[q * 8 + 4];
        const float d2 = sD2[e];
        uint32_t* dst = &sM[e * 40 + (q >> 1) * 8 + (q & 1)];
        {   // pair 0: k = q*8 + 0,1
            const float v0 = silu_f(bf_lo(aw.x) + bf_lo(bw.x) + d2 * wva.x + bva.x);
            const float v1 = silu_f(bf_hi(aw.x) + bf_hi(bw.x) + d2 * wva.y + bva.y);
            dst[0] = pack_bf16(v0, v1);
        }
        {   // pair 1: k = q*8 + 2,3
            const float v0 = silu_f(bf_lo(aw.y) + bf_lo(bw.y) + d2 * wva.z + bva.z);
            const float v1 = silu_f(bf_hi(aw.y) + bf_hi(bw.y) + d2 * wva.w + bva.w);
            dst[2] = pack_bf16(v0, v1);
        }
        {   // pair 2: k = q*8 + 4,5
            const float v0 = silu_f(bf_lo(aw.z) + bf_lo(bw.z) + d2 * wvb.x + bvb.x);
            const float v1 = silu_f(bf_hi(aw.z) + bf_hi(bw.z) + d2 * wvb.y + bvb.y);
            dst[4] = pack_bf16(v0, v1);
        }
        {   // pair 3: k = q*8 + 6,7
            const float v0 = silu_f(bf_lo(aw.w) + bf_lo(bw.w) + d2 * wvb.z + bvb.z);
            const float v1 = silu_f(bf_hi(aw.w) + bf_hi(bw.w) + d2 * wvb.w + bvb.w);
            dst[6] = pack_bf16(v0, v1);
        }
    }
    __syncthreads();

    float acc[8][4];
#pragma unroll
    for (int j = 0; j < 8; j++)
#pragma unroll
        for (int q = 0; q < 4; q++) acc[j][q] = 0.f;

#pragma unroll
    for (int g = 0; g < 4; g++) {
        uint32_t af[4], bf[2];
        const int r = warp * 16 + gq;
        const uint2 lo = *(const uint2*)&sM[r * 40 + g * 8 + 2 * tq];
        const uint2 hi = *(const uint2*)&sM[(r + 8) * 40 + g * 8 + 2 * tq];
        af[0] = lo.x; af[1] = hi.x; af[2] = lo.y; af[3] = hi.y;
#pragma unroll
        for (int j = 0; j < 8; j++) {
            const int c = j * 8 + gq;
            const uint2 b = *(const uint2*)&sW2[c * 40 + g * 8 + 2 * tq];
            bf[0] = b.x; bf[1] = b.y;
            mma_bf16(acc[j], af, bf);
        }
    }

    // epilogue: silu(+b2); dh scatter via f16x2 reductions
    const int r0 = warp * 16 + gq;
    const int n0 = sSrc[r0], n1 = sSrc[r0 + 8];
    float part0 = 0.f, part1 = 0.f;
#pragma unroll
    for (int j = 0; j < 8; j++) {
        const int c = j * 8 + tq * 2;
        const float bb0 = sB2[c], bb1 = sB2[c + 1];
        const float px0 = sPx[c], px1 = sPx[c + 1];
        const float v0 = silu_f(acc[j][0] + bb0);
        const float v1 = silu_f(acc[j][1] + bb1);
        const float v2 = silu_f(acc[j][2] + bb0);
        const float v3 = silu_f(acc[j][3] + bb1);
        part0 += v0 * px0 + v1 * px1;
        part1 += v2 * px0 + v3 * px1;
        red_add_h2(g_dh + (size_t)n0 * 64 + c, v0, v1);
        red_add_h2(g_dh + (size_t)n1 * 64 + c, v2, v3);
    }
    part0 += __shfl_xor_sync(0xffffffffu, part0, 1);
    part0 += __shfl_xor_sync(0xffffffffu, part0, 2);
    part1 += __shfl_xor_sync(0xffffffffu, part1, 1);
    part1 += __shfl_xor_sync(0xffffffffu, part1, 2);
    if (tq == 0) {
        atomicAdd(&g_dx[(size_t)n0 * 3 + 0], part0 * sDirx[r0]);
        atomicAdd(&g_dx[(size_t)n0 * 3 + 1], part0 * sDiry[r0]);
        atomicAdd(&g_dx[(size_t)n0 * 3 + 2], part0 * sDirz[r0]);
        atomicAdd(&g_dx[(size_t)n1 * 3 + 0], part1 * sDirx[r0 + 8]);
        atomicAdd(&g_dx[(size_t)n1 * 3 + 1], part1 * sDiry[r0 + 8]);
        atomicAdd(&g_dx[(size_t)n1 * 3 + 2], part1 * sDirz[r0 + 8]);
    }
}

// ---------------- launch ----------------
extern "C" void kernel_launch(void* const* d_in, const int* in_sizes, int n_in,
                              void* d_out, int out_size) {
    const float* x   = (const float*)d_in[0];
    const float* h   = (const float*)d_in[1];
    const int*   ei  = (const int*)d_in[2];
    const float* pw1 = (const float*)d_in[3];
    const float* pb1 = (const float*)d_in[4];
    const float* pw2 = (const float*)d_in[5];
    const float* pb2 = (const float*)d_in[6];
    const float* pxw = (const float*)d_in[7];
    const float* hw1 = (const float*)d_in[8];
    const float* hb1 = (const float*)d_in[9];
    const float* hw2 = (const float*)d_in[10];
    const float* hb2 = (const float*)d_in[11];

    float* out   = (float*)d_out;
    float* out_x = out;
    float* out_h = out + (size_t)BN * 3;

    const int GSMEM = 2 * 6144 * (int)sizeof(float);                   // 49152 B
    const int FSMEM = (6144 + 64 * 72) * (int)sizeof(float);           // 43008 B
    const int EDGE_SMEM = (2560 + 128 * 40) * (int)sizeof(float);      // 30720 B
    cudaFuncSetAttribute(gemm_p, cudaFuncAttributeMaxDynamicSharedMemorySize, GSMEM);
    cudaFuncSetAttribute(gemm_fused, cudaFuncAttributeMaxDynamicSharedMemorySize, FSMEM);
    cudaFuncSetAttribute(edge_kernel, cudaFuncAttributeMaxDynamicSharedMemorySize, EDGE_SMEM);

    prep_kernel<<<64, 256>>>(pw1, hw1, hw2, pw2);
    gemm_p<<<512 + 256, 256, GSMEM>>>(h);
    edge_kernel<<<NE / EPB, 256, EDGE_SMEM>>>(x, ei, pw1, pb1, pb2, pxw);
    gemm_fused<<<BN / 64 + 256, 256, FSMEM>>>(h, hb1, hb2, out_h, x, out_x);
}